// round 13
// baseline (speedup 1.0000x reference)
#include <cuda_runtime.h>
#include <cstdint>

#define NHEADS   16
#define M_TBL    524288
#define D_IN     32
#define HID      64
#define NOUT     3
#define TILE     128
#define THREADS  256
#define NTILES   16384           // 16384 * 128 = 2,097,152
#define GRID     296             // persistent: 2 CTAs per SM
#define STR      128

__constant__ __align__(16) float cW1[D_IN * HID];
__constant__ __align__(16) float cW2[HID * HID];
__constant__ __align__(16) float cW3[HID * HID];
__constant__ __align__(16) float cW4[HID * NOUT];
__constant__ __align__(16) float cb1[HID];
__constant__ __align__(16) float cb2[HID];
__constant__ __align__(16) float cb3[HID];
__constant__ __align__(16) float cb4[NOUT];

#define BUF_FLOATS (HID * STR)               // 8192 floats = 32 KB
#define SMEM_BYTES (2 * BUF_FLOATS * 4)      // 65536 -> 2 CTAs/SM

#define FMA2(acc, a, w) \
    asm("fma.rn.f32x2 %0, %1, %2, %0;" : "+l"(acc) : "l"(a), "l"(w))
#define PACK2(d, s) \
    asm("mov.b64 %0, {%1, %1};" : "=l"(d) : "f"(s))
#define UNPACK2(lo, hi, s) \
    asm("mov.b64 {%0, %1}, %2;" : "=f"(lo), "=f"(hi) : "l"(s))

typedef unsigned long long ull;

// One layer, ping-pong: read A, write B (disjoint).
// Warp owns j-block [8w, 8w+8); lane owns 4 points (lane*4..+3).
// acc[p*4 + jp] = j-pair (jw+2jp, jw+2jp+1) for point lane4+p.
// Per k-step: 1 LDS.128 + 2 LDC.128 + 4 PACK2 + 16 FFMA2.
template<int L, int K>
__device__ __forceinline__ void layer(const float* __restrict__ A,
                                      float* __restrict__ B,
                                      int jw, int lane4)
{
    ull acc[16];
    {
        ulonglong2 b01, b23;
        if constexpr (L == 1) {
            b01 = *reinterpret_cast<const ulonglong2*>(&cb1[jw]);
            b23 = *reinterpret_cast<const ulonglong2*>(&cb1[jw + 4]);
        } else if constexpr (L == 2) {
            b01 = *reinterpret_cast<const ulonglong2*>(&cb2[jw]);
            b23 = *reinterpret_cast<const ulonglong2*>(&cb2[jw + 4]);
        } else {
            b01 = *reinterpret_cast<const ulonglong2*>(&cb3[jw]);
            b23 = *reinterpret_cast<const ulonglong2*>(&cb3[jw + 4]);
        }
        #pragma unroll
        for (int p = 0; p < 4; p++) {
            acc[p*4 + 0] = b01.x; acc[p*4 + 1] = b01.y;
            acc[p*4 + 2] = b23.x; acc[p*4 + 3] = b23.y;
        }
    }

    #pragma unroll 8
    for (int k = 0; k < K; k++) {
        const float4 a = *reinterpret_cast<const float4*>(&A[k * STR + lane4]);
        ull d0, d1, d2, d3;
        PACK2(d0, a.x); PACK2(d1, a.y); PACK2(d2, a.z); PACK2(d3, a.w);

        ulonglong2 w01, w23;   // 4 natural j-pairs via 2 LDC.128 (warp-uniform)
        if constexpr (L == 1) {
            w01 = *reinterpret_cast<const ulonglong2*>(&cW1[k * HID + jw]);
            w23 = *reinterpret_cast<const ulonglong2*>(&cW1[k * HID + jw + 4]);
        } else if constexpr (L == 2) {
            w01 = *reinterpret_cast<const ulonglong2*>(&cW2[k * HID + jw]);
            w23 = *reinterpret_cast<const ulonglong2*>(&cW2[k * HID + jw + 4]);
        } else {
            w01 = *reinterpret_cast<const ulonglong2*>(&cW3[k * HID + jw]);
            w23 = *reinterpret_cast<const ulonglong2*>(&cW3[k * HID + jw + 4]);
        }

        FMA2(acc[ 0], d0, w01.x); FMA2(acc[ 1], d0, w01.y);
        FMA2(acc[ 2], d0, w23.x); FMA2(acc[ 3], d0, w23.y);
        FMA2(acc[ 4], d1, w01.x); FMA2(acc[ 5], d1, w01.y);
        FMA2(acc[ 6], d1, w23.x); FMA2(acc[ 7], d1, w23.y);
        FMA2(acc[ 8], d2, w01.x); FMA2(acc[ 9], d2, w01.y);
        FMA2(acc[10], d2, w23.x); FMA2(acc[11], d2, w23.y);
        FMA2(acc[12], d3, w01.x); FMA2(acc[13], d3, w01.y);
        FMA2(acc[14], d3, w23.x); FMA2(acc[15], d3, w23.y);
    }

    // relu + store this warp's 8 rows
    #pragma unroll
    for (int jp = 0; jp < 4; jp++) {
        float lo[4], hi[4];
        #pragma unroll
        for (int p = 0; p < 4; p++) {
            UNPACK2(lo[p], hi[p], acc[p*4 + jp]);
            lo[p] = fmaxf(lo[p], 0.0f);
            hi[p] = fmaxf(hi[p], 0.0f);
        }
        const int j0 = jw + 2 * jp;
        *reinterpret_cast<float4*>(&B[j0 * STR + lane4]) =
            make_float4(lo[0], lo[1], lo[2], lo[3]);
        *reinterpret_cast<float4*>(&B[(j0 + 1) * STR + lane4]) =
            make_float4(hi[0], hi[1], hi[2], hi[3]);
    }
}

__global__ __launch_bounds__(THREADS, 2)
void ngp_2cta_kernel(const int* __restrict__ idx,
                     const float* __restrict__ tables,
                     float* __restrict__ out)
{
    extern __shared__ float sm[];
    float* buf0 = sm;                 // input (rows 0..31) + L2 output
    float* buf1 = sm + BUF_FLOATS;    // L1, L3 outputs

    const int tid   = threadIdx.x;
    const int wid   = tid >> 5;
    const int lane  = tid & 31;
    const int jw    = wid * 8;        // 8 warps x 8 j-cols = 64
    const int lane4 = lane * 4;       // lane's 4 points
    const int gp = tid >> 1;          // gather: point (2 threads/point)
    const int gh = (tid & 1) * 8;     // gather: head start

    // ---- gather first tile into buf0 rows 0..31 ----
    {
        const int* ip = idx + ((long)blockIdx.x * TILE + gp) * NHEADS + gh;
        const int4 i0 = *reinterpret_cast<const int4*>(ip);
        const int4 i1 = *reinterpret_cast<const int4*>(ip + 4);
        const int ii[8] = { i0.x, i0.y, i0.z, i0.w, i1.x, i1.y, i1.z, i1.w };
        #pragma unroll
        for (int i = 0; i < 8; i++) {
            const float2 v = *reinterpret_cast<const float2*>(
                tables + ((long)(gh + i) * M_TBL + ii[i]) * 2);
            buf0[(2 * (gh + i)    ) * STR + gp] = v.x;
            buf0[(2 * (gh + i) + 1) * STR + gp] = v.y;
        }
    }
    __syncthreads();

    for (long t = blockIdx.x; t < NTILES; t += GRID) {
        const long pbase = (long)t * TILE;
        const bool hasNext = (t + GRID) < NTILES;

        // idx LDG for NEXT tile (hidden under layer 1)
        int4 ni0 = make_int4(0,0,0,0), ni1 = make_int4(0,0,0,0);
        if (hasNext) {
            const int* ip = idx + ((t + GRID) * TILE + gp) * NHEADS + gh;
            ni0 = *reinterpret_cast<const int4*>(ip);
            ni1 = *reinterpret_cast<const int4*>(ip + 4);
        }

        // layer 1: buf0 -> buf1
        layer<1, D_IN>(buf0, buf1, jw, lane4);
        __syncthreads();                               // [1]

        // table LDGs for next tile (hidden under L2/L3)
        float2 nv[8];
        if (hasNext) {
            const int nii[8] = { ni0.x, ni0.y, ni0.z, ni0.w,
                                 ni1.x, ni1.y, ni1.z, ni1.w };
            #pragma unroll
            for (int i = 0; i < 8; i++)
                nv[i] = *reinterpret_cast<const float2*>(
                    tables + ((long)(gh + i) * M_TBL + nii[i]) * 2);
        }

        // layer 2: buf1 -> buf0
        layer<2, HID>(buf1, buf0, jw, lane4);
        __syncthreads();                               // [2]

        // layer 3: buf0 -> buf1
        layer<3, HID>(buf0, buf1, jw, lane4);
        __syncthreads();                               // [3]

        // buf0 is dead: park NEXT tile's gather (concurrent with L4)
        if (hasNext) {
            #pragma unroll
            for (int i = 0; i < 8; i++) {
                buf0[(2 * (gh + i)    ) * STR + gp] = nv[i].x;
                buf0[(2 * (gh + i) + 1) * STR + gp] = nv[i].y;
            }
        }

        // layer 4: buf1 -> out, 2 threads/point (k halves) + shfl combine
        {
            const int p  = tid >> 1;
            const int kb = (tid & 1) * 32;
            float o0 = 0.f, o1 = 0.f, o2 = 0.f;
            #pragma unroll 8
            for (int k = kb; k < kb + 32; k++) {
                const float a = buf1[k * STR + p];
                o0 = fmaf(a, cW4[k * NOUT + 0], o0);
                o1 = fmaf(a, cW4[k * NOUT + 1], o1);
                o2 = fmaf(a, cW4[k * NOUT + 2], o2);
            }
            o0 += __shfl_down_sync(0xFFFFFFFFu, o0, 1);
            o1 += __shfl_down_sync(0xFFFFFFFFu, o1, 1);
            o2 += __shfl_down_sync(0xFFFFFFFFu, o2, 1);
            if ((tid & 1) == 0) {
                float* op = out + (pbase + p) * NOUT;
                op[0] = o0 + cb4[0];
                op[1] = o1 + cb4[1];
                op[2] = o2 + cb4[2];
            }
        }
        __syncthreads();                               // [4]
    }
}

extern "C" void kernel_launch(void* const* d_in, const int* in_sizes, int n_in,
                              void* d_out, int out_size)
{
    static int init = 0;
    if (!init) {
        cudaFuncSetAttribute(ngp_2cta_kernel,
                             cudaFuncAttributeMaxDynamicSharedMemorySize,
                             SMEM_BYTES);
        init = 1;
    }

    cudaMemcpyToSymbolAsync(cW1, d_in[2], D_IN*HID*sizeof(float), 0,
                            cudaMemcpyDeviceToDevice, 0);
    cudaMemcpyToSymbolAsync(cb1, d_in[3], HID*sizeof(float), 0,
                            cudaMemcpyDeviceToDevice, 0);
    cudaMemcpyToSymbolAsync(cW2, d_in[4], HID*HID*sizeof(float), 0,
                            cudaMemcpyDeviceToDevice, 0);
    cudaMemcpyToSymbolAsync(cb2, d_in[5], HID*sizeof(float), 0,
                            cudaMemcpyDeviceToDevice, 0);
    cudaMemcpyToSymbolAsync(cW3, d_in[6], HID*HID*sizeof(float), 0,
                            cudaMemcpyDeviceToDevice, 0);
    cudaMemcpyToSymbolAsync(cb3, d_in[7], HID*sizeof(float), 0,
                            cudaMemcpyDeviceToDevice, 0);
    cudaMemcpyToSymbolAsync(cW4, d_in[8], HID*NOUT*sizeof(float), 0,
                            cudaMemcpyDeviceToDevice, 0);
    cudaMemcpyToSymbolAsync(cb4, d_in[9], NOUT*sizeof(float), 0,
                            cudaMemcpyDeviceToDevice, 0);

    ngp_2cta_kernel<<<GRID, THREADS, SMEM_BYTES>>>(
        (const int*)d_in[0], (const float*)d_in[1], (float*)d_out);
}

// round 15
// speedup vs baseline: 1.4035x; 1.4035x over previous
#include <cuda_runtime.h>
#include <cstdint>

#define NHEADS   16
#define M_TBL    524288
#define D_IN     32
#define HID      64
#define NOUT     3
#define TILE     256
#define THREADS  512
#define NTILES   8192            // 8192 * 256 = 2,097,152
#define GRID     148             // persistent: 1 CTA (512 thr) per SM
#define STR      256

__constant__ __align__(16) float cW1[D_IN * HID];
__constant__ __align__(16) float cW2[HID * HID];
__constant__ __align__(16) float cW3[HID * HID];
__constant__ __align__(16) float cW4[HID * NOUT];
__constant__ __align__(16) float cb1[HID];
__constant__ __align__(16) float cb2[HID];
__constant__ __align__(16) float cb3[HID];
__constant__ __align__(16) float cb4[NOUT];

#define BUF_FLOATS (HID * STR)               // 16384 floats = 64 KB
#define SMEM_BYTES (2 * BUF_FLOATS * 4)      // 131072 -> 1 CTA/SM

#define FMA2(acc, a, b) \
    asm("fma.rn.f32x2 %0, %1, %2, %0;" : "+l"(acc) : "l"(a), "l"(b))
#define PACK2(d, s) \
    asm("mov.b64 %0, {%1, %1};" : "=l"(d) : "f"(s))
#define UNPACK2(lo, hi, s) \
    asm("mov.b64 {%0, %1}, %2;" : "=f"(lo), "=f"(hi) : "l"(s))

typedef unsigned long long ull;

// compute one k-step from already-loaded registers
__device__ __forceinline__ void compute_k(const float4& aA, const float4& aB,
                                          const ulonglong2& wp, ull acc[16])
{
    ull d0, d1, d2, d3, e0, e1, e2, e3;
    PACK2(d0, aA.x); PACK2(d1, aA.y); PACK2(d2, aA.z); PACK2(d3, aA.w);
    PACK2(e0, aB.x); PACK2(e1, aB.y); PACK2(e2, aB.z); PACK2(e3, aB.w);
    FMA2(acc[ 0], d0, wp.x); FMA2(acc[ 1], d0, wp.y);
    FMA2(acc[ 2], d1, wp.x); FMA2(acc[ 3], d1, wp.y);
    FMA2(acc[ 4], d2, wp.x); FMA2(acc[ 5], d2, wp.y);
    FMA2(acc[ 6], d3, wp.x); FMA2(acc[ 7], d3, wp.y);
    FMA2(acc[ 8], e0, wp.x); FMA2(acc[ 9], e0, wp.y);
    FMA2(acc[10], e1, wp.x); FMA2(acc[11], e1, wp.y);
    FMA2(acc[12], e2, wp.x); FMA2(acc[13], e2, wp.y);
    FMA2(acc[14], e3, wp.x); FMA2(acc[15], e3, wp.y);
}

// One layer, ping-pong (read A, write B), software-pipelined k-loop:
// loads for k+1 are issued before the FMAs of k, hiding LDS/LDC latency.
// Warp owns j-block [jw, jw+4). Lane owns points lane4..+3 and 128+lane4..+3.
template<int L, int K>
__device__ __forceinline__ void layer(const float* __restrict__ A,
                                      float* __restrict__ B,
                                      int jw, int lane4)
{
    const float* Wc;
    const float* bc;
    if constexpr (L == 1)      { Wc = cW1; bc = cb1; }
    else if constexpr (L == 2) { Wc = cW2; bc = cb2; }
    else                       { Wc = cW3; bc = cb3; }

    ull acc[16];
    {
        const ulonglong2 b = *reinterpret_cast<const ulonglong2*>(&bc[jw]);
        #pragma unroll
        for (int p = 0; p < 4; p++) {
            acc[p*2 + 0] = b.x;     acc[p*2 + 1] = b.y;
            acc[8 + p*2 + 0] = b.x; acc[8 + p*2 + 1] = b.y;
        }
    }

    // prologue: k = 0 loads
    float4 cA = *reinterpret_cast<const float4*>(&A[lane4]);
    float4 cB = *reinterpret_cast<const float4*>(&A[128 + lane4]);
    ulonglong2 cw = *reinterpret_cast<const ulonglong2*>(&Wc[jw]);

    #pragma unroll 8
    for (int k = 0; k < K - 1; k++) {
        // issue k+1 loads BEFORE computing k
        const float4 nA =
            *reinterpret_cast<const float4*>(&A[(k+1) * STR + lane4]);
        const float4 nB =
            *reinterpret_cast<const float4*>(&A[(k+1) * STR + 128 + lane4]);
        const ulonglong2 nw =
            *reinterpret_cast<const ulonglong2*>(&Wc[(k+1) * HID + jw]);

        compute_k(cA, cB, cw, acc);

        cA = nA; cB = nB; cw = nw;
    }
    compute_k(cA, cB, cw, acc);    // epilogue: k = K-1

    // relu + store
    #pragma unroll
    for (int jp = 0; jp < 2; jp++) {
        float lo[8], hi[8];
        #pragma unroll
        for (int p = 0; p < 4; p++) {
            UNPACK2(lo[p],     hi[p],     acc[p*2 + jp]);
            UNPACK2(lo[4 + p], hi[4 + p], acc[8 + p*2 + jp]);
        }
        #pragma unroll
        for (int q = 0; q < 8; q++) {
            lo[q] = fmaxf(lo[q], 0.0f);
            hi[q] = fmaxf(hi[q], 0.0f);
        }
        const int j0 = jw + 2 * jp;
        *reinterpret_cast<float4*>(&B[j0 * STR + lane4]) =
            make_float4(lo[0], lo[1], lo[2], lo[3]);
        *reinterpret_cast<float4*>(&B[j0 * STR + 128 + lane4]) =
            make_float4(lo[4], lo[5], lo[6], lo[7]);
        *reinterpret_cast<float4*>(&B[(j0 + 1) * STR + lane4]) =
            make_float4(hi[0], hi[1], hi[2], hi[3]);
        *reinterpret_cast<float4*>(&B[(j0 + 1) * STR + 128 + lane4]) =
            make_float4(hi[4], hi[5], hi[6], hi[7]);
    }
}

__global__ __launch_bounds__(THREADS, 1)
void ngp_pl_kernel(const int* __restrict__ idx,
                   const float* __restrict__ tables,
                   float* __restrict__ out)
{
    extern __shared__ float sm[];
    float* buf0 = sm;                 // input (rows 0..31) + L2 output
    float* buf1 = sm + BUF_FLOATS;    // L1, L3 outputs

    const int tid   = threadIdx.x;
    const int wid   = tid >> 5;
    const int lane  = tid & 31;
    const int jw    = wid * 4;        // 16 warps x 4 j-cols = 64
    const int lane4 = lane * 4;
    const int gp = tid >> 1;          // gather: point (2 threads/point)
    const int gh = (tid & 1) * 8;     // gather: head start

    // ---- gather first tile into buf0 rows 0..31 ----
    {
        const int* ip = idx + ((long)blockIdx.x * TILE + gp) * NHEADS + gh;
        const int4 i0 = *reinterpret_cast<const int4*>(ip);
        const int4 i1 = *reinterpret_cast<const int4*>(ip + 4);
        const int ii[8] = { i0.x, i0.y, i0.z, i0.w, i1.x, i1.y, i1.z, i1.w };
        #pragma unroll
        for (int i = 0; i < 8; i++) {
            const float2 v = *reinterpret_cast<const float2*>(
                tables + ((long)(gh + i) * M_TBL + ii[i]) * 2);
            buf0[(2 * (gh + i)    ) * STR + gp] = v.x;
            buf0[(2 * (gh + i) + 1) * STR + gp] = v.y;
        }
    }
    __syncthreads();

    for (long t = blockIdx.x; t < NTILES; t += GRID) {
        const long pbase = (long)t * TILE;
        const bool hasNext = (t + GRID) < NTILES;

        // idx LDG for NEXT tile (hidden under layer 1)
        int4 ni0 = make_int4(0,0,0,0), ni1 = make_int4(0,0,0,0);
        if (hasNext) {
            const int* ip = idx + ((t + GRID) * TILE + gp) * NHEADS + gh;
            ni0 = *reinterpret_cast<const int4*>(ip);
            ni1 = *reinterpret_cast<const int4*>(ip + 4);
        }

        // layer 1: buf0 -> buf1
        layer<1, D_IN>(buf0, buf1, jw, lane4);
        __syncthreads();                               // [1]

        // table LDGs for next tile (hidden under L2/L3)
        float2 nv[8];
        if (hasNext) {
            const int nii[8] = { ni0.x, ni0.y, ni0.z, ni0.w,
                                 ni1.x, ni1.y, ni1.z, ni1.w };
            #pragma unroll
            for (int i = 0; i < 8; i++)
                nv[i] = *reinterpret_cast<const float2*>(
                    tables + ((long)(gh + i) * M_TBL + nii[i]) * 2);
        }

        // layer 2: buf1 -> buf0
        layer<2, HID>(buf1, buf0, jw, lane4);
        __syncthreads();                               // [2]

        // layer 3: buf0 -> buf1
        layer<3, HID>(buf0, buf1, jw, lane4);
        __syncthreads();                               // [3]

        // buf0 is dead: park NEXT tile's gather (concurrent with L4)
        if (hasNext) {
            #pragma unroll
            for (int i = 0; i < 8; i++) {
                buf0[(2 * (gh + i)    ) * STR + gp] = nv[i].x;
                buf0[(2 * (gh + i) + 1) * STR + gp] = nv[i].y;
            }
        }

        // layer 4: buf1 -> out, 2 threads/point (k halves) + shfl combine
        {
            const int p  = tid >> 1;
            const int kb = (tid & 1) * 32;
            float o0 = 0.f, o1 = 0.f, o2 = 0.f;
            #pragma unroll 8
            for (int k = kb; k < kb + 32; k++) {
                const float a = buf1[k * STR + p];
                o0 = fmaf(a, cW4[k * NOUT + 0], o0);
                o1 = fmaf(a, cW4[k * NOUT + 1], o1);
                o2 = fmaf(a, cW4[k * NOUT + 2], o2);
            }
            o0 += __shfl_down_sync(0xFFFFFFFFu, o0, 1);
            o1 += __shfl_down_sync(0xFFFFFFFFu, o1, 1);
            o2 += __shfl_down_sync(0xFFFFFFFFu, o2, 1);
            if ((tid & 1) == 0) {
                float* op = out + (pbase + p) * NOUT;
                op[0] = o0 + cb4[0];
                op[1] = o1 + cb4[1];
                op[2] = o2 + cb4[2];
            }
        }
        __syncthreads();                               // [4]
    }
}

extern "C" void kernel_launch(void* const* d_in, const int* in_sizes, int n_in,
                              void* d_out, int out_size)
{
    static int init = 0;
    if (!init) {
        cudaFuncSetAttribute(ngp_pl_kernel,
                             cudaFuncAttributeMaxDynamicSharedMemorySize,
                             SMEM_BYTES);
        init = 1;
    }

    cudaMemcpyToSymbolAsync(cW1, d_in[2], D_IN*HID*sizeof(float), 0,
                            cudaMemcpyDeviceToDevice, 0);
    cudaMemcpyToSymbolAsync(cb1, d_in[3], HID*sizeof(float), 0,
                            cudaMemcpyDeviceToDevice, 0);
    cudaMemcpyToSymbolAsync(cW2, d_in[4], HID*HID*sizeof(float), 0,
                            cudaMemcpyDeviceToDevice, 0);
    cudaMemcpyToSymbolAsync(cb2, d_in[5], HID*sizeof(float), 0,
                            cudaMemcpyDeviceToDevice, 0);
    cudaMemcpyToSymbolAsync(cW3, d_in[6], HID*HID*sizeof(float), 0,
                            cudaMemcpyDeviceToDevice, 0);
    cudaMemcpyToSymbolAsync(cb3, d_in[7], HID*sizeof(float), 0,
                            cudaMemcpyDeviceToDevice, 0);
    cudaMemcpyToSymbolAsync(cW4, d_in[8], HID*NOUT*sizeof(float), 0,
                            cudaMemcpyDeviceToDevice, 0);
    cudaMemcpyToSymbolAsync(cb4, d_in[9], NOUT*sizeof(float), 0,
                            cudaMemcpyDeviceToDevice, 0);

    ngp_pl_kernel<<<GRID, THREADS, SMEM_BYTES>>>(
        (const int*)d_in[0], (const float*)d_in[1], (float*)d_out);
}